// round 2
// baseline (speedup 1.0000x reference)
#include <cuda_runtime.h>
#include <math.h>

// Problem dims
#define BD    128      // batch
#define SLEN  256      // sequence length
#define EDIM  512      // embedding dim
#define HDIM  1024     // hidden dim
#define ODIM  10       // output classes
#define NG    4096     // 4 gates * HDIM

// ---------------------------------------------------------------------------
// Scratch (static __device__ globals; no allocation at runtime)
// ---------------------------------------------------------------------------
__device__ int   g_is64;                                   // x dtype flag
__device__ float g_gatesx[(long)SLEN * BD * NG];           // 512 MB: x-projections [S][B][4H]
__device__ float g_h[2][BD * HDIM];                        // double-buffered hidden state
__device__ float g_c[BD * HDIM];                           // cell state

// packed dual fp32 FMA (FFMA2) — only reachable via PTX fma.rn.f32x2
__device__ __forceinline__ float2 ffma2(float2 a, float2 b, float2 c) {
    float2 d;
    asm("fma.rn.f32x2 %0, %1, %2, %3;"
        : "=l"(reinterpret_cast<unsigned long long &>(d))
        : "l"(reinterpret_cast<unsigned long long &>(a)),
          "l"(reinterpret_cast<unsigned long long &>(b)),
          "l"(reinterpret_cast<unsigned long long &>(c)));
    return d;
}

// ---------------------------------------------------------------------------
// Detect whether x is int64 or int32 (JAX may silently demote int64->int32).
// For int64 little-endian data the odd 32-bit words are all 0 (tokens<50000).
// ---------------------------------------------------------------------------
__global__ void k_detect(const int* __restrict__ xw) {
    if (threadIdx.x == 0 && blockIdx.x == 0) {
        int zeros = 0;
        for (int i = 0; i < 64; i++)
            if (xw[2 * i + 1] == 0) zeros++;
        g_is64 = (zeros >= 60) ? 1 : 0;
    }
}

__global__ void k_init() {
    int i = blockIdx.x * blockDim.x + threadIdx.x;
    if (i < BD * HDIM) {
        g_h[0][i] = 0.f;
        g_c[i]    = 0.f;
    }
}

// ---------------------------------------------------------------------------
// Input-projection GEMM with fused embedding gather.
//   M = B*S = 32768 (row m -> b=m>>8, s=m&255, token=x[m])
//   N = 4096 (gate g = n>>10, col = n&1023), K = 512
//   out: g_gatesx[s][b][g*1024+col] = bias_g[col] + sum_k emb[tok][k]*W_g[col][k]
// Tile 128x128, BK=8, 256 threads, 8x8 per thread via packed FFMA2.
// ---------------------------------------------------------------------------
__global__ __launch_bounds__(256)
void k_igemm(const void* __restrict__ xv, const float* __restrict__ emb,
             const float* __restrict__ Wi, const float* __restrict__ Wf,
             const float* __restrict__ Wg, const float* __restrict__ Wo,
             const float* __restrict__ bi, const float* __restrict__ bf,
             const float* __restrict__ bg, const float* __restrict__ bo) {
    __shared__ float As[8][128];
    __shared__ float Bs[8][128];

    const int tid = threadIdx.x;
    const int tx = tid & 15, ty = tid >> 4;
    const int m0 = blockIdx.y * 128;
    const int n0 = blockIdx.x * 128;
    const int gate = n0 >> 10;
    const int col0 = n0 & 1023;
    const float* W    = (gate == 0) ? Wi : (gate == 1) ? Wf : (gate == 2) ? Wg : Wo;
    const float* bias = (gate == 0) ? bi : (gate == 1) ? bf : (gate == 2) ? bg : bo;

    const int rowA = tid >> 1, kpa = tid & 1;   // loader mapping (2 threads/row)
    const int m = m0 + rowA;
    long tok;
    if (g_is64) tok = (long)((const long long*)xv)[m];
    else        tok = (long)((const int*)xv)[m];
    const float* arow = emb + tok * EDIM + kpa * 4;
    const float* brow = W + (long)(col0 + rowA) * EDIM + kpa * 4;

    float2 acc[8][4];
#pragma unroll
    for (int i = 0; i < 8; i++)
#pragma unroll
        for (int j = 0; j < 4; j++) acc[i][j] = make_float2(0.f, 0.f);

    float4 ra = *(const float4*)(arow);
    float4 rb = *(const float4*)(brow);

    for (int k0 = 0; k0 < EDIM; k0 += 8) {
        As[kpa * 4 + 0][rowA] = ra.x; As[kpa * 4 + 1][rowA] = ra.y;
        As[kpa * 4 + 2][rowA] = ra.z; As[kpa * 4 + 3][rowA] = ra.w;
        Bs[kpa * 4 + 0][rowA] = rb.x; Bs[kpa * 4 + 1][rowA] = rb.y;
        Bs[kpa * 4 + 2][rowA] = rb.z; Bs[kpa * 4 + 3][rowA] = rb.w;
        __syncthreads();
        if (k0 + 8 < EDIM) {
            ra = *(const float4*)(arow + k0 + 8);
            rb = *(const float4*)(brow + k0 + 8);
        }
#pragma unroll
        for (int kk = 0; kk < 8; kk++) {
            float4 a0 = *(const float4*)&As[kk][ty * 8];
            float4 a1 = *(const float4*)&As[kk][ty * 8 + 4];
            float4 b0 = *(const float4*)&Bs[kk][tx * 8];
            float4 b1 = *(const float4*)&Bs[kk][tx * 8 + 4];
            float  av[8] = {a0.x, a0.y, a0.z, a0.w, a1.x, a1.y, a1.z, a1.w};
            float2 bp[4] = {{b0.x, b0.y}, {b0.z, b0.w}, {b1.x, b1.y}, {b1.z, b1.w}};
#pragma unroll
            for (int i = 0; i < 8; i++) {
                float2 ap = make_float2(av[i], av[i]);
#pragma unroll
                for (int j = 0; j < 4; j++) acc[i][j] = ffma2(ap, bp[j], acc[i][j]);
            }
        }
        __syncthreads();
    }

#pragma unroll
    for (int i = 0; i < 8; i++) {
        int mm = m0 + ty * 8 + i;
        int bb = mm >> 8, ss = mm & 255;
        float* orow = g_gatesx + ((long)ss * BD + bb) * NG + n0 + tx * 8;
#pragma unroll
        for (int j = 0; j < 4; j++) {
            float2 v = acc[i][j];
            v.x += bias[col0 + tx * 8 + j * 2];
            v.y += bias[col0 + tx * 8 + j * 2 + 1];
            *(float2*)(orow + j * 2) = v;
        }
    }
}

// ---------------------------------------------------------------------------
// One LSTM step, fully fused: gate GEMM (h @ Wh^T for 4 gates) + cell update.
// Grid: 128 blocks; block owns hidden cols [hh0, hh0+8) for all 4 gates and
// all 128 batch rows. Reads g_h[t&1], writes g_h[1-(t&1)] (no in-place race).
// ---------------------------------------------------------------------------
__global__ __launch_bounds__(256)
void k_step(int t,
            const float* __restrict__ Whi, const float* __restrict__ Whf,
            const float* __restrict__ Whg, const float* __restrict__ Who) {
    __shared__ float As[8][128];   // h tile, transposed  [k][m]
    __shared__ float Bs[8][32];    // weight tile, col = j*4 + gate

    const int tid = threadIdx.x;
    const int tj = tid & 7, tm = tid >> 3;       // tj: local col, tm: 4-row group
    const int hh0 = blockIdx.x * 8;
    const int par = t & 1;
    const float* hsrc = g_h[par];
    float*       hdst = g_h[1 - par];

    const int rowA = tid >> 1, kpa = tid & 1;
    const float* arow = hsrc + rowA * HDIM + kpa * 4;

    const float* brow = nullptr;
    int bcol = 0, kpb = 0;
    if (tid < 64) {
        bcol = tid >> 1; kpb = tid & 1;
        int g = bcol & 3, j = bcol >> 2;
        const float* Wsel = (g == 0) ? Whi : (g == 1) ? Whf : (g == 2) ? Whg : Who;
        brow = Wsel + (long)(hh0 + j) * HDIM + kpb * 4;
    }

    float2 acc[4][2];
#pragma unroll
    for (int i = 0; i < 4; i++) { acc[i][0] = make_float2(0.f, 0.f); acc[i][1] = make_float2(0.f, 0.f); }

    float4 ra = *(const float4*)(arow);
    float4 rb = (tid < 64) ? *(const float4*)(brow) : make_float4(0.f, 0.f, 0.f, 0.f);

    for (int k0 = 0; k0 < HDIM; k0 += 8) {
        As[kpa * 4 + 0][rowA] = ra.x; As[kpa * 4 + 1][rowA] = ra.y;
        As[kpa * 4 + 2][rowA] = ra.z; As[kpa * 4 + 3][rowA] = ra.w;
        if (tid < 64) {
            Bs[kpb * 4 + 0][bcol] = rb.x; Bs[kpb * 4 + 1][bcol] = rb.y;
            Bs[kpb * 4 + 2][bcol] = rb.z; Bs[kpb * 4 + 3][bcol] = rb.w;
        }
        __syncthreads();
        if (k0 + 8 < HDIM) {
            ra = *(const float4*)(arow + k0 + 8);
            if (tid < 64) rb = *(const float4*)(brow + k0 + 8);
        }
#pragma unroll
        for (int kk = 0; kk < 8; kk++) {
            float4 av  = *(const float4*)&As[kk][tm * 4];
            float2 b01 = *(const float2*)&Bs[kk][tj * 4];
            float2 b23 = *(const float2*)&Bs[kk][tj * 4 + 2];
            float  a[4] = {av.x, av.y, av.z, av.w};
#pragma unroll
            for (int i = 0; i < 4; i++) {
                float2 ap = make_float2(a[i], a[i]);
                acc[i][0] = ffma2(ap, b01, acc[i][0]);
                acc[i][1] = ffma2(ap, b23, acc[i][1]);
            }
        }
        __syncthreads();
    }

    const float* gx = g_gatesx + (long)t * BD * NG;
    const int hh = hh0 + tj;
#pragma unroll
    for (int i = 0; i < 4; i++) {
        int mrow = tm * 4 + i;
        const float* gxr = gx + (long)mrow * NG;
        float pi = acc[i][0].x + gxr[hh];
        float pf = acc[i][0].y + gxr[HDIM + hh];
        float pg = acc[i][1].x + gxr[2 * HDIM + hh];
        float po = acc[i][1].y + gxr[3 * HDIM + hh];
        float iv = 1.f / (1.f + expf(-pi));
        float fv = 1.f / (1.f + expf(-pf));
        float gv = tanhf(pg);
        float ov = 1.f / (1.f + expf(-po));
        int idx = mrow * HDIM + hh;
        float cn = fv * g_c[idx] + iv * gv;
        g_c[idx]  = cn;
        hdst[idx] = ov * tanhf(cn);
    }
}

// ---------------------------------------------------------------------------
// Final FC: out[b][o] = fc_b[o] + h_T[b] . fc_W[o]
// After 256 steps (even), the final h lives in g_h[0].
// ---------------------------------------------------------------------------
__global__ void k_fc(const float* __restrict__ fcW, const float* __restrict__ fcb,
                     float* __restrict__ out) {
    int b = blockIdx.x;
    int w = threadIdx.x >> 5, lane = threadIdx.x & 31;
    if (w >= ODIM) return;
    const float* hrow = g_h[0] + b * HDIM;
    const float* wrow = fcW + w * HDIM;
    float s = 0.f;
    for (int k = lane; k < HDIM; k += 32) s += hrow[k] * wrow[k];
#pragma unroll
    for (int off = 16; off; off >>= 1) s += __shfl_xor_sync(0xffffffffu, s, off);
    if (lane == 0) out[b * ODIM + w] = s + fcb[w];
}

// ---------------------------------------------------------------------------
extern "C" void kernel_launch(void* const* d_in, const int* in_sizes, int n_in,
                              void* d_out, int out_size) {
    const void*  x   = d_in[0];
    const float* emb = (const float*)d_in[1];
    const float* Wii = (const float*)d_in[2];
    const float* bii = (const float*)d_in[3];
    const float* Whi = (const float*)d_in[4];
    const float* Wif = (const float*)d_in[5];
    const float* bif = (const float*)d_in[6];
    const float* Whf = (const float*)d_in[7];
    const float* Wig = (const float*)d_in[8];
    const float* big = (const float*)d_in[9];
    const float* Whg = (const float*)d_in[10];
    const float* Wio = (const float*)d_in[11];
    const float* bio = (const float*)d_in[12];
    const float* Who = (const float*)d_in[13];
    const float* fcW = (const float*)d_in[14];
    const float* fcb = (const float*)d_in[15];
    float* out = (float*)d_out;

    k_detect<<<1, 32>>>((const int*)x);
    k_init<<<(BD * HDIM + 255) / 256, 256>>>();

    dim3 g1(NG / 128, (BD * SLEN) / 128);
    k_igemm<<<g1, 256>>>(x, emb, Wii, Wif, Wig, Wio, bii, bif, big, bio);

    for (int t = 0; t < SLEN; t++)
        k_step<<<HDIM / 8, 256>>>(t, Whi, Whf, Whg, Who);

    k_fc<<<BD, 320>>>(fcW, fcb, out);
}

// round 3
// speedup vs baseline: 1.7556x; 1.7556x over previous
#include <cuda_runtime.h>
#include <cuda_bf16.h>
#include <math.h>
#include <stdint.h>

// Problem dims
#define BD    128
#define SLEN  256
#define EDIM  512
#define HDIM  1024
#define ODIM  10
#define NG    4096      // 4 gates * HDIM
#define MTOT  (BD*SLEN) // 32768

// ---------------------------------------------------------------------------
// Device scratch (no runtime allocation)
// ---------------------------------------------------------------------------
__device__ int   g_is64;
__device__ float g_gatesx[(long)SLEN * BD * NG];          // [s][b][4H] fp32
__device__ float g_h[BD * HDIM];                          // final-h fp32 (for FC)
__device__ float g_c[BD * HDIM];                          // cell state

// bf16 split operands
__device__ __nv_bfloat16 g_h_hi[2][BD * HDIM];            // h double-buffered, [b][k]
__device__ __nv_bfloat16 g_h_lo[2][BD * HDIM];
__device__ __nv_bfloat16 g_Whp_hi[(long)NG * HDIM];       // recurrent W packed [n][k], n=hblk*64+g*16+j
__device__ __nv_bfloat16 g_Whp_lo[(long)NG * HDIM];
__device__ __nv_bfloat16 g_Wip_hi[(long)NG * EDIM];       // input W packed [n][k], n=g*1024+col
__device__ __nv_bfloat16 g_Wip_lo[(long)NG * EDIM];
__device__ __nv_bfloat16 g_e_hi[(long)MTOT * EDIM];       // gathered embeddings split
__device__ __nv_bfloat16 g_e_lo[(long)MTOT * EDIM];

// ---------------------------------------------------------------------------
__device__ __forceinline__ void bsplit(float v, __nv_bfloat16& hi, __nv_bfloat16& lo) {
    hi = __float2bfloat16_rn(v);
    lo = __float2bfloat16_rn(v - __bfloat162float(hi));
}

__device__ __forceinline__ void mma16816(float& d0, float& d1, float& d2, float& d3,
                                         uint32_t a0, uint32_t a1, uint32_t a2, uint32_t a3,
                                         uint32_t b0, uint32_t b1) {
    asm volatile("mma.sync.aligned.m16n8k16.row.col.f32.bf16.bf16.f32 "
                 "{%0,%1,%2,%3}, {%4,%5,%6,%7}, {%8,%9}, {%0,%1,%2,%3};"
                 : "+f"(d0), "+f"(d1), "+f"(d2), "+f"(d3)
                 : "r"(a0), "r"(a1), "r"(a2), "r"(a3), "r"(b0), "r"(b1));
}

// ---------------------------------------------------------------------------
__global__ void k_detect(const int* __restrict__ xw) {
    if (threadIdx.x == 0 && blockIdx.x == 0) {
        int zeros = 0;
        for (int i = 0; i < 64; i++)
            if (xw[2 * i + 1] == 0) zeros++;
        g_is64 = (zeros >= 60) ? 1 : 0;
    }
}

__global__ void k_init() {
    int i = blockIdx.x * blockDim.x + threadIdx.x;
    if (i < BD * HDIM) {
        g_c[i] = 0.f;
        g_h_hi[0][i] = __float2bfloat16(0.f);
        g_h_lo[0][i] = __float2bfloat16(0.f);
    }
}

// gather embedding rows + bf16 split
__global__ void k_emb_split(const void* __restrict__ xv, const float* __restrict__ emb) {
    int m = blockIdx.x;
    long tok = g_is64 ? (long)((const long long*)xv)[m] : (long)((const int*)xv)[m];
    const float* src = emb + tok * EDIM;
    for (int k = threadIdx.x; k < EDIM; k += blockDim.x) {
        __nv_bfloat16 hi, lo;
        bsplit(src[k], hi, lo);
        g_e_hi[(long)m * EDIM + k] = hi;
        g_e_lo[(long)m * EDIM + k] = lo;
    }
}

// pack input-gate weights: n = g*1024 + col, row-major over k
__global__ void k_pack_wi(const float* __restrict__ Wi, const float* __restrict__ Wf,
                          const float* __restrict__ Wg, const float* __restrict__ Wo) {
    int n = blockIdx.x;
    int g = n >> 10, col = n & 1023;
    const float* src = ((g == 0) ? Wi : (g == 1) ? Wf : (g == 2) ? Wg : Wo) + (long)col * EDIM;
    for (int k = threadIdx.x; k < EDIM; k += blockDim.x) {
        __nv_bfloat16 hi, lo;
        bsplit(src[k], hi, lo);
        g_Wip_hi[(long)n * EDIM + k] = hi;
        g_Wip_lo[(long)n * EDIM + k] = lo;
    }
}

// pack recurrent weights interleaved: n = hblk*64 + g*16 + j, h = hblk*16 + j
__global__ void k_pack_wh(const float* __restrict__ Wi, const float* __restrict__ Wf,
                          const float* __restrict__ Wg, const float* __restrict__ Wo) {
    int n = blockIdx.x;
    int hb = n >> 6, r = n & 63, g = r >> 4, j = r & 15;
    int h = hb * 16 + j;
    const float* src = ((g == 0) ? Wi : (g == 1) ? Wf : (g == 2) ? Wg : Wo) + (long)h * HDIM;
    for (int k = threadIdx.x; k < HDIM; k += blockDim.x) {
        __nv_bfloat16 hi, lo;
        bsplit(src[k], hi, lo);
        g_Whp_hi[(long)n * HDIM + k] = hi;
        g_Whp_lo[(long)n * HDIM + k] = lo;
    }
}

// ---------------------------------------------------------------------------
// Input projection GEMM (tensor cores): [32768 x 512] @ [512 x 4096] -> gatesx
// CTA tile 128x128, 256 threads (8 warps, warp tile 32x64), kc=16, 2-stage.
// ---------------------------------------------------------------------------
#define IP 24   // smem pitch (bf16) for kc=16
__global__ __launch_bounds__(256)
void k_igemm_tc(const float* __restrict__ bi, const float* __restrict__ bf2,
                const float* __restrict__ bg, const float* __restrict__ bo) {
    __shared__ __align__(16) __nv_bfloat16 sm[2][4][128 * IP];   // 48KB

    const int tid = threadIdx.x;
    const int n0 = blockIdx.x * 128;
    const int M0 = blockIdx.y * 128;

    const int w = tid >> 5, lane = tid & 31;
    const int g = lane >> 2, tig = lane & 3;
    const int m0w = (w >> 1) * 32, n0w = (w & 1) * 64;

    // copy plan: 512 rows of 32B; thread owns rows {tid, tid+256}
    const __nv_bfloat16* gp[2];
    int sel[2], idx[2];
#pragma unroll
    for (int a = 0; a < 2; a++) {
        int r = tid + a * 256;
        sel[a] = r >> 7; idx[a] = r & 127;
        if (sel[a] == 0)      gp[a] = g_e_hi  + (long)(M0 + idx[a]) * EDIM;
        else if (sel[a] == 1) gp[a] = g_e_lo  + (long)(M0 + idx[a]) * EDIM;
        else if (sel[a] == 2) gp[a] = g_Wip_hi + (long)(n0 + idx[a]) * EDIM;
        else                  gp[a] = g_Wip_lo + (long)(n0 + idx[a]) * EDIM;
    }

    float acc[2][8][4];
#pragma unroll
    for (int mt = 0; mt < 2; mt++)
#pragma unroll
        for (int nt = 0; nt < 8; nt++)
#pragma unroll
            for (int q = 0; q < 4; q++) acc[mt][nt][q] = 0.f;

    uint4 p[2][2];
#pragma unroll
    for (int a = 0; a < 2; a++) { p[a][0] = ((const uint4*)gp[a])[0]; p[a][1] = ((const uint4*)gp[a])[1]; }
#pragma unroll
    for (int a = 0; a < 2; a++) {
        uint4* d = (uint4*)(&sm[0][sel[a]][idx[a] * IP]);
        d[0] = p[a][0]; d[1] = p[a][1];
    }
    __syncthreads();

    const int NSTAGE = EDIM / 16;   // 32
    for (int s = 0; s < NSTAGE; s++) {
        int buf = s & 1;
        bool more = (s + 1 < NSTAGE);
        if (more) {
#pragma unroll
            for (int a = 0; a < 2; a++) {
                gp[a] += 16;
                p[a][0] = ((const uint4*)gp[a])[0]; p[a][1] = ((const uint4*)gp[a])[1];
            }
        }
        const __nv_bfloat16* Ah = sm[buf][0];
        const __nv_bfloat16* Al = sm[buf][1];
        const __nv_bfloat16* Bh = sm[buf][2];
        const __nv_bfloat16* Bl = sm[buf][3];
        const int kb = 2 * tig;

        uint32_t aH[2][4], aL[2][4], bH[8][2], bL[8][2];
#pragma unroll
        for (int mt = 0; mt < 2; mt++) {
            int rw = (m0w + mt * 16 + g) * IP + kb;
            aH[mt][0] = *(const uint32_t*)(Ah + rw);
            aH[mt][1] = *(const uint32_t*)(Ah + rw + 8 * IP);
            aH[mt][2] = *(const uint32_t*)(Ah + rw + 8);
            aH[mt][3] = *(const uint32_t*)(Ah + rw + 8 * IP + 8);
            aL[mt][0] = *(const uint32_t*)(Al + rw);
            aL[mt][1] = *(const uint32_t*)(Al + rw + 8 * IP);
            aL[mt][2] = *(const uint32_t*)(Al + rw + 8);
            aL[mt][3] = *(const uint32_t*)(Al + rw + 8 * IP + 8);
        }
#pragma unroll
        for (int nt = 0; nt < 8; nt++) {
            int cw = (n0w + nt * 8 + g) * IP + kb;
            bH[nt][0] = *(const uint32_t*)(Bh + cw);
            bH[nt][1] = *(const uint32_t*)(Bh + cw + 8);
            bL[nt][0] = *(const uint32_t*)(Bl + cw);
            bL[nt][1] = *(const uint32_t*)(Bl + cw + 8);
        }
#pragma unroll
        for (int mt = 0; mt < 2; mt++)
#pragma unroll
            for (int nt = 0; nt < 8; nt++) {
                float* d = acc[mt][nt];
                mma16816(d[0], d[1], d[2], d[3], aH[mt][0], aH[mt][1], aH[mt][2], aH[mt][3], bH[nt][0], bH[nt][1]);
                mma16816(d[0], d[1], d[2], d[3], aL[mt][0], aL[mt][1], aL[mt][2], aL[mt][3], bH[nt][0], bH[nt][1]);
                mma16816(d[0], d[1], d[2], d[3], aH[mt][0], aH[mt][1], aH[mt][2], aH[mt][3], bL[nt][0], bL[nt][1]);
            }

        if (more) {
#pragma unroll
            for (int a = 0; a < 2; a++) {
                uint4* d = (uint4*)(&sm[buf ^ 1][sel[a]][idx[a] * IP]);
                d[0] = p[a][0]; d[1] = p[a][1];
            }
        }
        __syncthreads();
    }

    // epilogue: add bias, write fp32 gatesx
#pragma unroll
    for (int mt = 0; mt < 2; mt++) {
        int r0 = m0w + mt * 16 + g;
#pragma unroll
        for (int nt = 0; nt < 8; nt++) {
            int col  = n0w + nt * 8 + 2 * tig;
            int ncol = n0 + col;
            int gate = ncol >> 10, hcol = ncol & 1023;
            const float* bptr = (gate == 0) ? bi : (gate == 1) ? bf2 : (gate == 2) ? bg : bo;
            float bv0 = bptr[hcol], bv1 = bptr[hcol + 1];
#pragma unroll
            for (int half = 0; half < 2; half++) {
                int mrow = M0 + r0 + half * 8;
                int b = mrow >> 8, ss = mrow & 255;
                float2 v = make_float2(acc[mt][nt][half * 2] + bv0, acc[mt][nt][half * 2 + 1] + bv1);
                *(float2*)(g_gatesx + ((long)ss * BD + b) * NG + ncol) = v;
            }
        }
    }
}

// ---------------------------------------------------------------------------
// One LSTM step, tensor cores + fused cell update.
// Grid (64, 2): blockIdx.x = hblk (16 hidden cols x 4 gates), blockIdx.y = batch half.
// CTA tile 64(M)x64(N), 128 threads (4 warps, warp tile 32x32), kc=32, 2-stage.
// ---------------------------------------------------------------------------
#define SP 40   // smem pitch (bf16) for kc=32
__global__ __launch_bounds__(128)
void k_step_tc(int t) {
    __shared__ __align__(16) __nv_bfloat16 sm[2][4][64 * SP];   // 40KB

    const int tid = threadIdx.x;
    const int hblk = blockIdx.x;
    const int m0 = blockIdx.y * 64;
    const int n0 = hblk * 64;
    const int par = t & 1, nxt = 1 - par;

    const int w = tid >> 5, lane = tid & 31;
    const int g = lane >> 2, tig = lane & 3;
    const int m0w = (w >> 1) * 32, n0w = (w & 1) * 32;

    // copy plan: 256 rows of 64B; thread owns rows {tid, tid+128}
    const __nv_bfloat16* gp[2];
    int sel[2], idx[2];
#pragma unroll
    for (int a = 0; a < 2; a++) {
        int r = tid + a * 128;
        sel[a] = r >> 6; idx[a] = r & 63;
        if (sel[a] == 0)      gp[a] = g_h_hi[par] + (long)(m0 + idx[a]) * HDIM;
        else if (sel[a] == 1) gp[a] = g_h_lo[par] + (long)(m0 + idx[a]) * HDIM;
        else if (sel[a] == 2) gp[a] = g_Whp_hi + (long)(n0 + idx[a]) * HDIM;
        else                  gp[a] = g_Whp_lo + (long)(n0 + idx[a]) * HDIM;
    }

    float acc[2][4][4];
#pragma unroll
    for (int mt = 0; mt < 2; mt++)
#pragma unroll
        for (int nt = 0; nt < 4; nt++)
#pragma unroll
            for (int q = 0; q < 4; q++) acc[mt][nt][q] = 0.f;

    uint4 p[2][4];
#pragma unroll
    for (int a = 0; a < 2; a++)
#pragma unroll
        for (int q = 0; q < 4; q++) p[a][q] = ((const uint4*)gp[a])[q];
#pragma unroll
    for (int a = 0; a < 2; a++) {
        uint4* d = (uint4*)(&sm[0][sel[a]][idx[a] * SP]);
#pragma unroll
        for (int q = 0; q < 4; q++) d[q] = p[a][q];
    }
    __syncthreads();

    const int NSTAGE = HDIM / 32;   // 32
    for (int s = 0; s < NSTAGE; s++) {
        int buf = s & 1;
        bool more = (s + 1 < NSTAGE);
        if (more) {
#pragma unroll
            for (int a = 0; a < 2; a++) {
                gp[a] += 32;
#pragma unroll
                for (int q = 0; q < 4; q++) p[a][q] = ((const uint4*)gp[a])[q];
            }
        }
        const __nv_bfloat16* Ah = sm[buf][0];
        const __nv_bfloat16* Al = sm[buf][1];
        const __nv_bfloat16* Bh = sm[buf][2];
        const __nv_bfloat16* Bl = sm[buf][3];

#pragma unroll
        for (int kk = 0; kk < 2; kk++) {
            const int kb = kk * 16 + 2 * tig;
            uint32_t aH[2][4], aL[2][4], bH[4][2], bL[4][2];
#pragma unroll
            for (int mt = 0; mt < 2; mt++) {
                int rw = (m0w + mt * 16 + g) * SP + kb;
                aH[mt][0] = *(const uint32_t*)(Ah + rw);
                aH[mt][1] = *(const uint32_t*)(Ah + rw + 8 * SP);
                aH[mt][2] = *(const uint32_t*)(Ah + rw + 8);
                aH[mt][3] = *(const uint32_t*)(Ah + rw + 8 * SP + 8);
                aL[mt][0] = *(const uint32_t*)(Al + rw);
                aL[mt][1] = *(const uint32_t*)(Al + rw + 8 * SP);
                aL[mt][2] = *(const uint32_t*)(Al + rw + 8);
                aL[mt][3] = *(const uint32_t*)(Al + rw + 8 * SP + 8);
            }
#pragma unroll
            for (int nt = 0; nt < 4; nt++) {
                int cw = (n0w + nt * 8 + g) * SP + kb;
                bH[nt][0] = *(const uint32_t*)(Bh + cw);
                bH[nt][1] = *(const uint32_t*)(Bh + cw + 8);
                bL[nt][0] = *(const uint32_t*)(Bl + cw);
                bL[nt][1] = *(const uint32_t*)(Bl + cw + 8);
            }
#pragma unroll
            for (int mt = 0; mt < 2; mt++)
#pragma unroll
                for (int nt = 0; nt < 4; nt++) {
                    float* d = acc[mt][nt];
                    mma16816(d[0], d[1], d[2], d[3], aH[mt][0], aH[mt][1], aH[mt][2], aH[mt][3], bH[nt][0], bH[nt][1]);
                    mma16816(d[0], d[1], d[2], d[3], aL[mt][0], aL[mt][1], aL[mt][2], aL[mt][3], bH[nt][0], bH[nt][1]);
                    mma16816(d[0], d[1], d[2], d[3], aH[mt][0], aH[mt][1], aH[mt][2], aH[mt][3], bL[nt][0], bL[nt][1]);
                }
        }

        if (more) {
#pragma unroll
            for (int a = 0; a < 2; a++) {
                uint4* d = (uint4*)(&sm[buf ^ 1][sel[a]][idx[a] * SP]);
#pragma unroll
                for (int q = 0; q < 4; q++) d[q] = p[a][q];
            }
        }
        __syncthreads();
    }

    // stage preacts in smem (alias): pre[64][68]
    float* pre = (float*)&sm[0][0][0];
#pragma unroll
    for (int mt = 0; mt < 2; mt++) {
        int r0 = m0w + mt * 16 + g;
#pragma unroll
        for (int nt = 0; nt < 4; nt++) {
            int col = n0w + nt * 8 + 2 * tig;
            *(float2*)&pre[r0 * 68 + col]       = make_float2(acc[mt][nt][0], acc[mt][nt][1]);
            *(float2*)&pre[(r0 + 8) * 68 + col] = make_float2(acc[mt][nt][2], acc[mt][nt][3]);
        }
    }
    __syncthreads();

    // fused cell update: 64 batch rows x 16 hidden cols
    for (int pidx = tid; pidx < 1024; pidx += 128) {
        int m = pidx >> 4, j = pidx & 15;
        int b = m0 + m;
        int h = hblk * 16 + j;
        const float* gxr = g_gatesx + ((long)t * BD + b) * NG;
        float pi = pre[m * 68 + j]      + gxr[h];
        float pf = pre[m * 68 + 16 + j] + gxr[HDIM + h];
        float pg = pre[m * 68 + 32 + j] + gxr[2 * HDIM + h];
        float po = pre[m * 68 + 48 + j] + gxr[3 * HDIM + h];
        float iv = 1.f / (1.f + expf(-pi));
        float fv = 1.f / (1.f + expf(-pf));
        float gv = tanhf(pg);
        float ov = 1.f / (1.f + expf(-po));
        int cidx = b * HDIM + h;
        float cn = fv * g_c[cidx] + iv * gv;
        g_c[cidx] = cn;
        float hn = ov * tanhf(cn);
        g_h[cidx] = hn;
        __nv_bfloat16 hi, lo;
        bsplit(hn, hi, lo);
        g_h_hi[nxt][cidx] = hi;
        g_h_lo[nxt][cidx] = lo;
    }
}

// ---------------------------------------------------------------------------
__global__ void k_fc(const float* __restrict__ fcW, const float* __restrict__ fcb,
                     float* __restrict__ out) {
    int b = blockIdx.x;
    int w = threadIdx.x >> 5, lane = threadIdx.x & 31;
    if (w >= ODIM) return;
    const float* hrow = g_h + b * HDIM;
    const float* wrow = fcW + w * HDIM;
    float s = 0.f;
    for (int k = lane; k < HDIM; k += 32) s += hrow[k] * wrow[k];
#pragma unroll
    for (int off = 16; off; off >>= 1) s += __shfl_xor_sync(0xffffffffu, s, off);
    if (lane == 0) out[b * ODIM + w] = s + fcb[w];
}

// ---------------------------------------------------------------------------
extern "C" void kernel_launch(void* const* d_in, const int* in_sizes, int n_in,
                              void* d_out, int out_size) {
    const void*  x   = d_in[0];
    const float* emb = (const float*)d_in[1];
    const float* Wii = (const float*)d_in[2];
    const float* bii = (const float*)d_in[3];
    const float* Whi = (const float*)d_in[4];
    const float* Wif = (const float*)d_in[5];
    const float* bif = (const float*)d_in[6];
    const float* Whf = (const float*)d_in[7];
    const float* Wig = (const float*)d_in[8];
    const float* big = (const float*)d_in[9];
    const float* Whg = (const float*)d_in[10];
    const float* Wio = (const float*)d_in[11];
    const float* bio = (const float*)d_in[12];
    const float* Who = (const float*)d_in[13];
    const float* fcW = (const float*)d_in[14];
    const float* fcb = (const float*)d_in[15];
    float* out = (float*)d_out;

    k_detect<<<1, 32>>>((const int*)x);
    k_init<<<(BD * HDIM + 255) / 256, 256>>>();
    k_emb_split<<<MTOT, 128>>>(x, emb);
    k_pack_wi<<<NG, 256>>>(Wii, Wif, Wig, Wio);
    k_pack_wh<<<NG, 256>>>(Whi, Whf, Whg, Who);

    k_igemm_tc<<<dim3(NG / 128, MTOT / 128), 256>>>(bii, bif, big, bio);

    for (int t = 0; t < SLEN; t++)
        k_step_tc<<<dim3(64, 2), 128>>>(t);

    k_fc<<<BD, 320>>>(fcW, fcb, out);
}

// round 4
// speedup vs baseline: 2.3926x; 1.3628x over previous
#include <cuda_runtime.h>
#include <cuda_bf16.h>
#include <math.h>
#include <stdint.h>

// Problem dims
#define BD    128
#define SLEN  256
#define EDIM  512
#define HDIM  1024
#define ODIM  10
#define NG    4096      // 4 gates * HDIM
#define MTOT  (BD*SLEN) // 32768

#define NCTA  128       // persistent step CTAs (1/SM, all resident; 128 <= 148)
#define NTH   256       // threads per persistent CTA (8 warps)

// ---------------------------------------------------------------------------
// Device scratch (no runtime allocation)
// ---------------------------------------------------------------------------
__device__ int   g_is64;
// gatesx layout: [s][hb(128)][g(4)][b(128)][8]  (contiguous 16KB per (s,hb))
__device__ float g_gatesx[(long)SLEN * BD * NG];
__device__ float g_h[BD * HDIM];                          // final-h fp32 (for FC)

__device__ __nv_bfloat16 g_h_hi[2][BD * HDIM];            // h ping-pong, [b][k]
__device__ __nv_bfloat16 g_h_lo[2][BD * HDIM];
__device__ __nv_bfloat16 g_Whp_hi[(long)NG * HDIM];       // packed n = hb*32 + g*8 + j
__device__ __nv_bfloat16 g_Whp_lo[(long)NG * HDIM];
__device__ __nv_bfloat16 g_Wip_hi[(long)NG * EDIM];       // packed n = g*1024 + col
__device__ __nv_bfloat16 g_Wip_lo[(long)NG * EDIM];
__device__ __nv_bfloat16 g_e_hi[(long)MTOT * EDIM];
__device__ __nv_bfloat16 g_e_lo[(long)MTOT * EDIM];

// grid barrier (8 sub-counters, 256B strided to dodge LTS atomic serialization)
__device__ unsigned          g_bar_cnt[8 * 64];
__device__ volatile unsigned g_bar_gen[8 * 64];

// ---------------------------------------------------------------------------
__device__ __forceinline__ void bsplit(float v, __nv_bfloat16& hi, __nv_bfloat16& lo) {
    hi = __float2bfloat16_rn(v);
    lo = __float2bfloat16_rn(v - __bfloat162float(hi));
}

__device__ __forceinline__ void mma16816(float& d0, float& d1, float& d2, float& d3,
                                         uint32_t a0, uint32_t a1, uint32_t a2, uint32_t a3,
                                         uint32_t b0, uint32_t b1) {
    asm volatile("mma.sync.aligned.m16n8k16.row.col.f32.bf16.bf16.f32 "
                 "{%0,%1,%2,%3}, {%4,%5,%6,%7}, {%8,%9}, {%0,%1,%2,%3};"
                 : "+f"(d0), "+f"(d1), "+f"(d2), "+f"(d3)
                 : "r"(a0), "r"(a1), "r"(a2), "r"(a3), "r"(b0), "r"(b1));
}

__device__ __forceinline__ void cpasync16(void* s, const void* g) {
    unsigned sa = (unsigned)__cvta_generic_to_shared(s);
    asm volatile("cp.async.cg.shared.global [%0], [%1], 16;\n" :: "r"(sa), "l"(g));
}
#define CP_COMMIT() asm volatile("cp.async.commit_group;\n" ::: "memory")
template <int N> __device__ __forceinline__ void cp_wait() {
    asm volatile("cp.async.wait_group %0;\n" :: "n"(N) : "memory");
}

// ---------------------------------------------------------------------------
__global__ void k_detect(const int* __restrict__ xw) {
    if (threadIdx.x == 0 && blockIdx.x == 0) {
        int zeros = 0;
        for (int i = 0; i < 64; i++)
            if (xw[2 * i + 1] == 0) zeros++;
        g_is64 = (zeros >= 60) ? 1 : 0;
    }
}

__global__ void k_init() {
    int i = blockIdx.x * blockDim.x + threadIdx.x;
    if (i < BD * HDIM) {
        g_h_hi[0][i] = __float2bfloat16(0.f);
        g_h_lo[0][i] = __float2bfloat16(0.f);
    }
    if (i < 8 * 64) {
        g_bar_cnt[i] = 0u;
        g_bar_gen[i] = 0u;
    }
}

__global__ void k_emb_split(const void* __restrict__ xv, const float* __restrict__ emb) {
    int m = blockIdx.x;
    long tok = g_is64 ? (long)((const long long*)xv)[m] : (long)((const int*)xv)[m];
    const float* src = emb + tok * EDIM;
    for (int k = threadIdx.x; k < EDIM; k += blockDim.x) {
        __nv_bfloat16 hi, lo;
        bsplit(src[k], hi, lo);
        g_e_hi[(long)m * EDIM + k] = hi;
        g_e_lo[(long)m * EDIM + k] = lo;
    }
}

__global__ void k_pack_wi(const float* __restrict__ Wi, const float* __restrict__ Wf,
                          const float* __restrict__ Wg, const float* __restrict__ Wo) {
    int n = blockIdx.x;
    int g = n >> 10, col = n & 1023;
    const float* src = ((g == 0) ? Wi : (g == 1) ? Wf : (g == 2) ? Wg : Wo) + (long)col * EDIM;
    for (int k = threadIdx.x; k < EDIM; k += blockDim.x) {
        __nv_bfloat16 hi, lo;
        bsplit(src[k], hi, lo);
        g_Wip_hi[(long)n * EDIM + k] = hi;
        g_Wip_lo[(long)n * EDIM + k] = lo;
    }
}

// pack recurrent weights: n = hb*32 + g*8 + j  ->  hidden h = hb*8 + j, gate g
__global__ void k_pack_wh(const float* __restrict__ Wi, const float* __restrict__ Wf,
                          const float* __restrict__ Wg, const float* __restrict__ Wo) {
    int n = blockIdx.x;
    int hb = n >> 5, r = n & 31, g = r >> 3, j = r & 7;
    int h = hb * 8 + j;
    const float* src = ((g == 0) ? Wi : (g == 1) ? Wf : (g == 2) ? Wg : Wo) + (long)h * HDIM;
    for (int k = threadIdx.x; k < HDIM; k += blockDim.x) {
        __nv_bfloat16 hi, lo;
        bsplit(src[k], hi, lo);
        g_Whp_hi[(long)n * HDIM + k] = hi;
        g_Whp_lo[(long)n * HDIM + k] = lo;
    }
}

// ---------------------------------------------------------------------------
// Input projection GEMM (tensor cores): [32768 x 512] @ [512 x 4096]
// CTA tile 128x128, 256 threads, kc=16, 2-stage. Epilogue writes the
// step-friendly gatesx layout [s][hb][g][b][8].
// ---------------------------------------------------------------------------
#define IP 24
__global__ __launch_bounds__(256)
void k_igemm_tc(const float* __restrict__ bi, const float* __restrict__ bf2,
                const float* __restrict__ bg, const float* __restrict__ bo) {
    __shared__ __align__(16) __nv_bfloat16 sm[2][4][128 * IP];

    const int tid = threadIdx.x;
    const int n0 = blockIdx.x * 128;
    const int M0 = blockIdx.y * 128;

    const int w = tid >> 5, lane = tid & 31;
    const int g = lane >> 2, tig = lane & 3;
    const int m0w = (w >> 1) * 32, n0w = (w & 1) * 64;

    const __nv_bfloat16* gp[2];
    int sel[2], idx[2];
#pragma unroll
    for (int a = 0; a < 2; a++) {
        int r = tid + a * 256;
        sel[a] = r >> 7; idx[a] = r & 127;
        if (sel[a] == 0)      gp[a] = g_e_hi   + (long)(M0 + idx[a]) * EDIM;
        else if (sel[a] == 1) gp[a] = g_e_lo   + (long)(M0 + idx[a]) * EDIM;
        else if (sel[a] == 2) gp[a] = g_Wip_hi + (long)(n0 + idx[a]) * EDIM;
        else                  gp[a] = g_Wip_lo + (long)(n0 + idx[a]) * EDIM;
    }

    float acc[2][8][4];
#pragma unroll
    for (int mt = 0; mt < 2; mt++)
#pragma unroll
        for (int nt = 0; nt < 8; nt++)
#pragma unroll
            for (int q = 0; q < 4; q++) acc[mt][nt][q] = 0.f;

    uint4 p[2][2];
#pragma unroll
    for (int a = 0; a < 2; a++) { p[a][0] = ((const uint4*)gp[a])[0]; p[a][1] = ((const uint4*)gp[a])[1]; }
#pragma unroll
    for (int a = 0; a < 2; a++) {
        uint4* d = (uint4*)(&sm[0][sel[a]][idx[a] * IP]);
        d[0] = p[a][0]; d[1] = p[a][1];
    }
    __syncthreads();

    const int NSTAGE = EDIM / 16;
    for (int s = 0; s < NSTAGE; s++) {
        int buf = s & 1;
        bool more = (s + 1 < NSTAGE);
        if (more) {
#pragma unroll
            for (int a = 0; a < 2; a++) {
                gp[a] += 16;
                p[a][0] = ((const uint4*)gp[a])[0]; p[a][1] = ((const uint4*)gp[a])[1];
            }
        }
        const __nv_bfloat16* Ah = sm[buf][0];
        const __nv_bfloat16* Al = sm[buf][1];
        const __nv_bfloat16* Bh = sm[buf][2];
        const __nv_bfloat16* Bl = sm[buf][3];
        const int kb = 2 * tig;

        uint32_t aH[2][4], aL[2][4], bH[8][2], bL[8][2];
#pragma unroll
        for (int mt = 0; mt < 2; mt++) {
            int rw = (m0w + mt * 16 + g) * IP + kb;
            aH[mt][0] = *(const uint32_t*)(Ah + rw);
            aH[mt][1] = *(const uint32_t*)(Ah + rw + 8 * IP);
            aH[mt][2] = *(const uint32_t*)(Ah + rw + 8);
            aH[mt][3] = *(const uint32_t*)(Ah + rw + 8 * IP + 8);
            aL[mt][0] = *(const uint32_t*)(Al + rw);
            aL[mt][1] = *(const uint32_t*)(Al + rw + 8 * IP);
            aL[mt][2] = *(const uint32_t*)(Al + rw + 8);
            aL[mt][3] = *(const uint32_t*)(Al + rw + 8 * IP + 8);
        }
#pragma unroll
        for (int nt = 0; nt < 8; nt++) {
            int cw = (n0w + nt * 8 + g) * IP + kb;
            bH[nt][0] = *(const uint32_t*)(Bh + cw);
            bH[nt][1] = *(const uint32_t*)(Bh + cw + 8);
            bL[nt][0] = *(const uint32_t*)(Bl + cw);
            bL[nt][1] = *(const uint32_t*)(Bl + cw + 8);
        }
#pragma unroll
        for (int mt = 0; mt < 2; mt++)
#pragma unroll
            for (int nt = 0; nt < 8; nt++) {
                float* d = acc[mt][nt];
                mma16816(d[0], d[1], d[2], d[3], aH[mt][0], aH[mt][1], aH[mt][2], aH[mt][3], bH[nt][0], bH[nt][1]);
                mma16816(d[0], d[1], d[2], d[3], aL[mt][0], aL[mt][1], aL[mt][2], aL[mt][3], bH[nt][0], bH[nt][1]);
                mma16816(d[0], d[1], d[2], d[3], aH[mt][0], aH[mt][1], aH[mt][2], aH[mt][3], bL[nt][0], bL[nt][1]);
            }

        if (more) {
#pragma unroll
            for (int a = 0; a < 2; a++) {
                uint4* d = (uint4*)(&sm[buf ^ 1][sel[a]][idx[a] * IP]);
                d[0] = p[a][0]; d[1] = p[a][1];
            }
        }
        __syncthreads();
    }

    // epilogue: add bias, write [s][hb][g][b][8] layout
#pragma unroll
    for (int mt = 0; mt < 2; mt++) {
        int r0 = m0w + mt * 16 + g;
#pragma unroll
        for (int nt = 0; nt < 8; nt++) {
            int col  = n0w + nt * 8 + 2 * tig;
            int ncol = n0 + col;
            int gate = ncol >> 10, hcol = ncol & 1023;
            int hb = hcol >> 3, j = hcol & 7;
            const float* bptr = (gate == 0) ? bi : (gate == 1) ? bf2 : (gate == 2) ? bg : bo;
            float bv0 = bptr[hcol], bv1 = bptr[hcol + 1];
#pragma unroll
            for (int half = 0; half < 2; half++) {
                int mrow = M0 + r0 + half * 8;
                int b = mrow >> 8, ss = mrow & 255;
                float2 v = make_float2(acc[mt][nt][half * 2] + bv0, acc[mt][nt][half * 2 + 1] + bv1);
                long off = ((((long)ss * 128 + hb) * 4 + gate) * 128 + b) * 8 + j;
                *(float2*)(g_gatesx + off) = v;
            }
        }
    }
}

// ---------------------------------------------------------------------------
// Persistent LSTM step kernel: 128 CTAs x 256 threads, all 256 steps.
// CTA owns 32 gate-rows (8 hidden cols x 4 gates); weights resident in SMEM.
// Per step: stream h (hi/lo) via cp.async (kc=64, double-buffered), MMA,
// fused cell update with c in SMEM, grid barrier.
// ---------------------------------------------------------------------------
#define WPITCH 1032   // bf16 pitch for W rows (k=1024)
#define HPITCH 72     // bf16 pitch for h stage rows (kc=64)
#define PPITCH 40     // fp32 pitch for preact staging
#define SMEM_PERSIST (2*32*WPITCH*2 + 2*2*128*HPITCH*2 + 4096*4 + 1024*4)

__device__ __forceinline__ void gridbar(unsigned gen) {
    __syncthreads();
    if (threadIdx.x == 0) {
        __threadfence();
        int c = (blockIdx.x & 7) * 64;
        unsigned prev = atomicAdd(&g_bar_cnt[c], 1u);
        if (prev == (NCTA / 8) - 1) {
            g_bar_cnt[c] = 0u;
            __threadfence();
            g_bar_gen[c] = gen;
        }
        bool done = false;
        while (!done) {
            done = true;
#pragma unroll
            for (int q = 0; q < 8; q++)
                if (g_bar_gen[q * 64] < gen) done = false;
        }
        __threadfence();
    }
    __syncthreads();
}

__global__ __launch_bounds__(NTH, 1)
void k_lstm_persist() {
    extern __shared__ __align__(16) unsigned char smraw[];
    __nv_bfloat16* sWhi = (__nv_bfloat16*)smraw;                  // [32][WPITCH]
    __nv_bfloat16* sWlo = sWhi + 32 * WPITCH;
    __nv_bfloat16* sH   = sWlo + 32 * WPITCH;                     // [2][2][128][HPITCH]
    float* sGates = (float*)(sH + 2 * 2 * 128 * HPITCH);          // [4][128][8]
    float* sC     = sGates + 4096;                                // [128][8]
    float* pre    = (float*)sH;                                   // alias (buf0 region)

    const int tid = threadIdx.x;
    const int cta = blockIdx.x;
    const int w = tid >> 5, lane = tid & 31;
    const int g = lane >> 2, tig = lane & 3;
    const int m0w = (w >> 1) * 32;        // 4-way split of M=128
    const int n0w = (w & 1) * 16;         // 2-way split of N=32

    // ---- load resident weights (once) ----
    {
        int r = tid >> 2, q = tid & 3;    // 64 rows (32 hi + 32 lo), 4 thr/row
        const __nv_bfloat16* src = ((r < 32) ? g_Whp_hi : g_Whp_lo) + (long)(cta * 32 + (r & 31)) * HDIM;
        __nv_bfloat16* dst = ((r < 32) ? sWhi : sWlo) + (r & 31) * WPITCH;
#pragma unroll
        for (int i = 0; i < 32; i++)
            *(uint4*)(dst + q * 256 + i * 8) = *(const uint4*)(src + q * 256 + i * 8);
    }
    for (int i = tid; i < 1024; i += NTH) sC[i] = 0.f;
    __syncthreads();

    const int rowC = tid & 127, hlC = tid >> 7;   // cp.async plan: 1 row/thread

    for (int t = 0; t < SLEN; t++) {
        const int par = t & 1;
        const __nv_bfloat16* hsrc = (hlC ? g_h_lo[par] : g_h_hi[par]) + rowC * HDIM;
        __nv_bfloat16* const stageDst0 = sH + ((0 * 2 + hlC) * 128 + rowC) * HPITCH;
        __nv_bfloat16* const stageDst1 = sH + ((1 * 2 + hlC) * 128 + rowC) * HPITCH;

        // gates prefetch (16KB contiguous) + stage 0  -> group
        {
            const float* gsrc = g_gatesx + (((long)t * 128 + cta) * 4) * 1024;
#pragma unroll
            for (int a = 0; a < 4; a++) {
                int idx4 = (tid + a * 256) * 4;
                cpasync16(sGates + idx4, gsrc + idx4);
            }
#pragma unroll
            for (int i = 0; i < 8; i++) cpasync16(stageDst0 + i * 8, hsrc + 0 * 64 + i * 8);
            CP_COMMIT();
#pragma unroll
            for (int i = 0; i < 8; i++) cpasync16(stageDst1 + i * 8, hsrc + 1 * 64 + i * 8);
            CP_COMMIT();
        }

        float acc[2][2][4];
#pragma unroll
        for (int mt = 0; mt < 2; mt++)
#pragma unroll
            for (int nt = 0; nt < 2; nt++)
#pragma unroll
                for (int q = 0; q < 4; q++) acc[mt][nt][q] = 0.f;

        for (int s = 0; s < 16; s++) {
            cp_wait<1>();
            __syncthreads();
            const int buf = s & 1;
            const __nv_bfloat16* Ah = sH + ((buf * 2 + 0) * 128) * HPITCH;
            const __nv_bfloat16* Al = sH + ((buf * 2 + 1) * 128) * HPITCH;
            const int kcol = s * 64;

#pragma unroll
            for (int kk = 0; kk < 4; kk++) {
                const int kb = kk * 16 + 2 * tig;
                uint32_t aH[2][4], aL[2][4], bH[2][2], bL[2][2];
#pragma unroll
                for (int mt = 0; mt < 2; mt++) {
                    int rw = (m0w + mt * 16 + g) * HPITCH + kb;
                    aH[mt][0] = *(const uint32_t*)(Ah + rw);
                    aH[mt][1] = *(const uint32_t*)(Ah + rw + 8 * HPITCH);
                    aH[mt][2] = *(const uint32_t*)(Ah + rw + 8);
                    aH[mt][3] = *(const uint32_t*)(Ah + rw + 8 * HPITCH + 8);
                    aL[mt][0] = *(const uint32_t*)(Al + rw);
                    aL[mt][1] = *(const uint32_t*)(Al + rw + 8 * HPITCH);
                    aL[mt][2] = *(const uint32_t*)(Al + rw + 8);
                    aL[mt][3] = *(const uint32_t*)(Al + rw + 8 * HPITCH + 8);
                }
#pragma unroll
                for (int nt = 0; nt < 2; nt++) {
                    int cw = (n0w + nt * 8 + g) * WPITCH + kcol + kb;
                    bH[nt][0] = *(const uint32_t*)(sWhi + cw);
                    bH[nt][1] = *(const uint32_t*)(sWhi + cw + 8);
                    bL[nt][0] = *(const uint32_t*)(sWlo + cw);
                    bL[nt][1] = *(const uint32_t*)(sWlo + cw + 8);
                }
#pragma unroll
                for (int mt = 0; mt < 2; mt++)
#pragma unroll
                    for (int nt = 0; nt < 2; nt++) {
                        float* d = acc[mt][nt];
                        mma16816(d[0], d[1], d[2], d[3], aH[mt][0], aH[mt][1], aH[mt][2], aH[mt][3], bH[nt][0], bH[nt][1]);
                        mma16816(d[0], d[1], d[2], d[3], aL[mt][0], aL[mt][1], aL[mt][2], aL[mt][3], bH[nt][0], bH[nt][1]);
                        mma16816(d[0], d[1], d[2], d[3], aH[mt][0], aH[mt][1], aH[mt][2], aH[mt][3], bL[nt][0], bL[nt][1]);
                    }
            }
            __syncthreads();
            if (s + 2 < 16) {
                const int nbuf = s & 1;   // (s+2)&1
                __nv_bfloat16* dst = (nbuf == 0) ? stageDst0 : stageDst1;
#pragma unroll
                for (int i = 0; i < 8; i++) cpasync16(dst + i * 8, hsrc + (s + 2) * 64 + i * 8);
            }
            CP_COMMIT();
        }

        // stage preacts (pre aliases buf0 region, unused after stage 14)
#pragma unroll
        for (int mt = 0; mt < 2; mt++) {
            int r0 = m0w + mt * 16 + g;
#pragma unroll
            for (int nt = 0; nt < 2; nt++) {
                int col = n0w + nt * 8 + 2 * tig;
                *(float2*)&pre[r0 * PPITCH + col]       = make_float2(acc[mt][nt][0], acc[mt][nt][1]);
                *(float2*)&pre[(r0 + 8) * PPITCH + col] = make_float2(acc[mt][nt][2], acc[mt][nt][3]);
            }
        }
        __syncthreads();

        // fused cell update: 128 b x 8 h per CTA
        const int nxt = 1 - par;
#pragma unroll
        for (int it = 0; it < 4; it++) {
            int pidx = tid + it * 256;            // 0..1023
            int b = pidx >> 3, j = pidx & 7;
            float pi = pre[b * PPITCH + 0 * 8 + j] + sGates[(0 * 128 + b) * 8 + j];
            float pf = pre[b * PPITCH + 1 * 8 + j] + sGates[(1 * 128 + b) * 8 + j];
            float pg = pre[b * PPITCH + 2 * 8 + j] + sGates[(2 * 128 + b) * 8 + j];
            float po = pre[b * PPITCH + 3 * 8 + j] + sGates[(3 * 128 + b) * 8 + j];
            float iv = 1.f / (1.f + expf(-pi));
            float fv = 1.f / (1.f + expf(-pf));
            float gv = tanhf(pg);
            float ov = 1.f / (1.f + expf(-po));
            float cn = fv * sC[pidx] + iv * gv;
            sC[pidx] = cn;
            float hn = ov * tanhf(cn);
            int gidx = b * HDIM + cta * 8 + j;
            __nv_bfloat16 hi, lo;
            bsplit(hn, hi, lo);
            g_h_hi[nxt][gidx] = hi;
            g_h_lo[nxt][gidx] = lo;
            if (t == SLEN - 1) g_h[gidx] = hn;
        }

        gridbar((unsigned)(t + 1));
    }
}

// ---------------------------------------------------------------------------
__global__ void k_fc(const float* __restrict__ fcW, const float* __restrict__ fcb,
                     float* __restrict__ out) {
    int b = blockIdx.x;
    int w = threadIdx.x >> 5, lane = threadIdx.x & 31;
    if (w >= ODIM) return;
    const float* hrow = g_h + b * HDIM;
    const float* wrow = fcW + w * HDIM;
    float s = 0.f;
    for (int k = lane; k < HDIM; k += 32) s += hrow[k] * wrow[k];
#pragma unroll
    for (int off = 16; off; off >>= 1) s += __shfl_xor_sync(0xffffffffu, s, off);
    if (lane == 0) out[b * ODIM + w] = s + fcb[w];
}

// ---------------------------------------------------------------------------
extern "C" void kernel_launch(void* const* d_in, const int* in_sizes, int n_in,
                              void* d_out, int out_size) {
    const void*  x   = d_in[0];
    const float* emb = (const float*)d_in[1];
    const float* Wii = (const float*)d_in[2];
    const float* bii = (const float*)d_in[3];
    const float* Whi = (const float*)d_in[4];
    const float* Wif = (const float*)d_in[5];
    const float* bif = (const float*)d_in[6];
    const float* Whf = (const float*)d_in[7];
    const float* Wig = (const float*)d_in[8];
    const float* big = (const float*)d_in[9];
    const float* Whg = (const float*)d_in[10];
    const float* Wio = (const float*)d_in[11];
    const float* bio = (const float*)d_in[12];
    const float* Who = (const float*)d_in[13];
    const float* fcW = (const float*)d_in[14];
    const float* fcb = (const float*)d_in[15];
    float* out = (float*)d_out;

    cudaFuncSetAttribute(k_lstm_persist, cudaFuncAttributeMaxDynamicSharedMemorySize,
                         SMEM_PERSIST);

    k_detect<<<1, 32>>>((const int*)x);
    k_init<<<(BD * HDIM + 255) / 256, 256>>>();
    k_emb_split<<<MTOT, 128>>>(x, emb);
    k_pack_wi<<<NG, 256>>>(Wii, Wif, Wig, Wio);
    k_pack_wh<<<NG, 256>>>(Whi, Whf, Whg, Who);

    k_igemm_tc<<<dim3(NG / 128, MTOT / 128), 256>>>(bii, bif, big, bio);

    k_lstm_persist<<<NCTA, NTH, SMEM_PERSIST>>>();

    k_fc<<<BD, 320>>>(fcW, fcb, out);
}